// round 15
// baseline (speedup 1.0000x reference)
#include <cuda_runtime.h>
#include <math.h>

#define N_IMG   65536
#define IMG_D   2048
#define N_CLS   2048
#define ATT_D   1024
#define HC      512
#define TSOFT   10.0f
#define THRESH  0.17364817766693041f
#define PROTO_GRID 296

// ---------------- scratch (static device memory; no allocation) ----------------
__device__ float g_a1[N_CLS * HC];
__device__ float g_a2[N_CLS * HC];
__device__ float g_b2[N_CLS * HC];
__device__ float g_rnorm[N_CLS];
__device__ float g_protos[N_CLS * IMG_D];
__device__ float g_attr_tf[N_CLS * ATT_D];
__device__ float g_ga_tf[ATT_D * HC];
__device__ float g_gv_tf[ATT_D * HC];
__device__ int   g_count[N_CLS];
__device__ int   g_offset[N_CLS];
__device__ int   g_cursor[N_CLS];
__device__ int   g_perm[N_IMG];
// candidate lists: worst case a full row fits -> overflow impossible.
__device__ int   g_cand_cnt[N_CLS];
__device__ int   g_cand_idx[N_CLS * N_CLS];
__device__ float g_cand_val[N_CLS * N_CLS];

__device__ __forceinline__ float f2tf(float x) {
    unsigned r;
    asm("cvt.rna.tf32.f32 %0, %1;" : "=r"(r) : "f"(x));
    return __uint_as_float(r);
}

// ---------------- pre-round inputs to tf32 (one launch) ----------------
#define A4  (N_CLS * ATT_D / 4)
#define G4  (ATT_D * HC / 4)
__global__ void round_all_kernel(const float* __restrict__ attr, const float* __restrict__ ga,
                                 const float* __restrict__ gv) {
    int i = blockIdx.x * blockDim.x + threadIdx.x;
    const float4* src;
    float4* dst;
    int j;
    if (i < A4)            { src = (const float4*)attr; dst = (float4*)g_attr_tf; j = i; }
    else if (i < A4 + G4)  { src = (const float4*)ga;   dst = (float4*)g_ga_tf;   j = i - A4; }
    else if (i < A4 + 2*G4){ src = (const float4*)gv;   dst = (float4*)g_gv_tf;   j = i - A4 - G4; }
    else return;
    float4 v = src[j];
    v.x = f2tf(v.x); v.y = f2tf(v.y); v.z = f2tf(v.z); v.w = f2tf(v.w);
    dst[j] = v;
}

// ---------------- segment mean chain (side stream) ----------------
__global__ void countscan_kernel(const int* __restrict__ labels) {
    __shared__ int cnt[N_CLS];
    __shared__ int b[1024];
    int t = threadIdx.x;
    cnt[t] = 0; cnt[t + 1024] = 0;
    __syncthreads();
    for (int i = t; i < N_IMG; i += 1024) atomicAdd(&cnt[labels[i]], 1);
    __syncthreads();
    b[t] = cnt[2 * t] + cnt[2 * t + 1];
    __syncthreads();
    for (int off = 1; off < 1024; off <<= 1) {
        int v = (t >= off) ? b[t - off] : 0;
        __syncthreads();
        b[t] += v;
        __syncthreads();
    }
    int excl = (t == 0) ? 0 : b[t - 1];
    g_count[2 * t]      = cnt[2 * t];
    g_count[2 * t + 1]  = cnt[2 * t + 1];
    g_offset[2 * t]     = excl;
    g_offset[2 * t + 1] = excl + cnt[2 * t];
    g_cursor[2 * t]     = excl;
    g_cursor[2 * t + 1] = excl + cnt[2 * t];
}

__global__ void scatter_kernel(const int* __restrict__ labels) {
    int i = blockIdx.x * blockDim.x + threadIdx.x;
    if (i < N_IMG) {
        int l = labels[i];
        int pos = atomicAdd(&g_cursor[l], 1);
        g_perm[pos] = i;
    }
}

// persistent proto: grid-stride over 4096 (class, half) items, 2 blocks/SM
__global__ void proto_kernel(const float* __restrict__ imgs) {
    for (int w = blockIdx.x; w < N_CLS * 2; w += PROTO_GRID) {
        int c = w >> 1;
        int col = (w & 1) * 1024 + threadIdx.x * 4;
        int cnt  = g_count[c];
        int base = g_offset[c];
        float4 acc = make_float4(0.f, 0.f, 0.f, 0.f);
        int r = 0;
        for (; r + 8 <= cnt; r += 8) {
            float4 v[8];
#pragma unroll
            for (int u = 0; u < 8; u++) {
                int idx = g_perm[base + r + u];
                v[u] = __ldcs((const float4*)(imgs + (size_t)idx * IMG_D + col));
            }
#pragma unroll
            for (int u = 0; u < 8; u++) {
                acc.x += v[u].x; acc.y += v[u].y; acc.z += v[u].z; acc.w += v[u].w;
            }
        }
        for (; r < cnt; r++) {
            int idx = g_perm[base + r];
            float4 v0 = __ldcs((const float4*)(imgs + (size_t)idx * IMG_D + col));
            acc.x += v0.x; acc.y += v0.y; acc.z += v0.z; acc.w += v0.w;
        }
        float inv = (cnt > 0) ? (1.0f / (float)cnt) : 0.0f;
        acc.x *= inv; acc.y *= inv; acc.z *= inv; acc.w *= inv;
        *(float4*)(g_protos + (size_t)c * IMG_D + col) = acc;
    }
}

// ---------------- MMA / cp.async primitives ----------------
__device__ __forceinline__ void mma_tf32(float* c, const unsigned* a, const unsigned* b) {
    asm volatile(
        "mma.sync.aligned.m16n8k8.row.col.f32.tf32.tf32.f32 "
        "{%0,%1,%2,%3}, {%4,%5,%6,%7}, {%8,%9}, {%0,%1,%2,%3};"
        : "+f"(c[0]), "+f"(c[1]), "+f"(c[2]), "+f"(c[3])
        : "r"(a[0]), "r"(a[1]), "r"(a[2]), "r"(a[3]), "r"(b[0]), "r"(b[1]));
}
__device__ __forceinline__ void cp16(unsigned dst, const float* src) {
    asm volatile("cp.async.cg.shared.global [%0], [%1], 16;" :: "r"(dst), "l"(src));
}
__device__ __forceinline__ void cp_commit() { asm volatile("cp.async.commit_group;"); }
__device__ __forceinline__ void cp_wait1()  { asm volatile("cp.async.wait_group 1;"); }

// ---------------- dual NN GEMM: z=0: a1 = attr@ga (tf32-rounded out); z=1: b2 = attr@gv ----------------
__global__ __launch_bounds__(256)
void gemm_nn_dual(const float* __restrict__ A, const float* __restrict__ B0,
                  const float* __restrict__ B1, float* __restrict__ C0, float* __restrict__ C1,
                  int M, int N, int K) {
    const int S = 3, BK = 32, BN = 64;
    const int SA = 36, SBN = 68;
    const int ASZ = 128 * SA, BSZ = BK * SBN;

    const float* B = (blockIdx.z == 0) ? B0 : B1;
    float* C       = (blockIdx.z == 0) ? C0 : C1;
    bool rout      = (blockIdx.z == 0);

    extern __shared__ float sm[];
    float* As = sm;
    float* Bs = sm + S * ASZ;
    unsigned asu = (unsigned)__cvta_generic_to_shared(As);
    unsigned bsu = (unsigned)__cvta_generic_to_shared(Bs);

    int t = threadIdx.x;
    int warp = t >> 5, lane = t & 31, g = lane >> 2, tig = lane & 3;
    int bm = blockIdx.y * 128, bn = blockIdx.x * BN;
    int wm = (warp >> 1) * 32, wn = (warp & 1) * (BN / 2);

    float c[2][4][4];
#pragma unroll
    for (int mi = 0; mi < 2; mi++)
#pragma unroll
        for (int ni = 0; ni < 4; ni++)
#pragma unroll
            for (int q = 0; q < 4; q++) c[mi][ni][q] = 0.f;

    auto load_stage = [&](int stg, int kt) {
        const int KC = BK / 4;
#pragma unroll
        for (int ch = t; ch < 32 * BK; ch += 256) {
            int row = ch / KC;
            int kq = (ch % KC) * 4;
            cp16(asu + (stg * ASZ + row * SA + kq) * 4, A + (size_t)(bm + row) * K + kt + kq);
        }
        const int NC = BN / 4;
#pragma unroll
        for (int ch = t; ch < (BK * BN) / 4; ch += 256) {
            int krow = ch / NC;
            int nq = (ch % NC) * 4;
            cp16(bsu + (stg * BSZ + krow * SBN + nq) * 4, B + (size_t)(kt + krow) * N + bn + nq);
        }
        cp_commit();
    };

    int T = K / BK;
    load_stage(0, 0);
    load_stage(1, BK);

    for (int kt = 0; kt < T; kt++) {
        cp_wait1();
        __syncthreads();
        int stg = kt % S;
        if (kt + S - 1 < T) load_stage((kt + S - 1) % S, (kt + S - 1) * BK);

        const float* Ast = As + stg * ASZ;
        const float* Bst = Bs + stg * BSZ;
#pragma unroll
        for (int ks = 0; ks < BK; ks += 8) {
            unsigned a[2][4], bf[4][2];
#pragma unroll
            for (int mi = 0; mi < 2; mi++) {
                int rb = wm + mi * 16;
                a[mi][0] = __float_as_uint(Ast[(rb + g) * SA + ks + tig]);
                a[mi][1] = __float_as_uint(Ast[(rb + g + 8) * SA + ks + tig]);
                a[mi][2] = __float_as_uint(Ast[(rb + g) * SA + ks + tig + 4]);
                a[mi][3] = __float_as_uint(Ast[(rb + g + 8) * SA + ks + tig + 4]);
            }
#pragma unroll
            for (int ni = 0; ni < 4; ni++) {
                int cb = wn + ni * 8 + g;
                bf[ni][0] = __float_as_uint(Bst[(ks + tig) * SBN + cb]);
                bf[ni][1] = __float_as_uint(Bst[(ks + tig + 4) * SBN + cb]);
            }
#pragma unroll
            for (int mi = 0; mi < 2; mi++)
#pragma unroll
                for (int ni = 0; ni < 4; ni++)
                    mma_tf32(c[mi][ni], a[mi], bf[ni]);
        }
    }

#pragma unroll
    for (int mi = 0; mi < 2; mi++) {
#pragma unroll
        for (int ni = 0; ni < 4; ni++) {
            int row = bm + wm + mi * 16 + g;
            int col = bn + wn + ni * 8 + tig * 2;
            float v0 = c[mi][ni][0], v1 = c[mi][ni][1];
            float v2 = c[mi][ni][2], v3 = c[mi][ni][3];
            if (rout) { v0 = f2tf(v0); v1 = f2tf(v1); v2 = f2tf(v2); v3 = f2tf(v3); }
            *(float2*)(C + (size_t)row * N + col)       = make_float2(v0, v1);
            *(float2*)(C + (size_t)(row + 8) * N + col) = make_float2(v2, v3);
        }
    }
}

// ---------------- NT Gram + in-register threshold -> candidate lists (no D matrix!) ----------------
__device__ __forceinline__ void cand_emit(int i, int j, float vs) {
    if (vs > THRESH) {
        int p = atomicAdd(&g_cand_cnt[i], 1);
        g_cand_idx[(size_t)i * N_CLS + p] = j;
        g_cand_val[(size_t)i * N_CLS + p] = vs;
    }
}

__global__ __launch_bounds__(256)
void gemm_nt_cand(const float* __restrict__ A, const float* __restrict__ rn, int N, int K) {
    const int S = 3, BK = 32, BN = 128;
    const int SA = 36;
    const int ASZ = 128 * SA, BSZ = BN * SA;

    extern __shared__ float sm[];
    float* As = sm;
    float* Bs = sm + S * ASZ;
    unsigned asu = (unsigned)__cvta_generic_to_shared(As);
    unsigned bsu = (unsigned)__cvta_generic_to_shared(Bs);

    int t = threadIdx.x;
    int warp = t >> 5, lane = t & 31, g = lane >> 2, tig = lane & 3;

    int bi = blockIdx.x, r = 0, rowlen = N / 128;
    while (bi >= rowlen) { bi -= rowlen; r++; rowlen--; }
    int bm = r * 128;
    int bn = (r + bi) * 128;
    bool diag = (bm == bn);

    int wm = (warp >> 1) * 32, wn = (warp & 1) * 64;

    float c[2][8][4];
#pragma unroll
    for (int mi = 0; mi < 2; mi++)
#pragma unroll
        for (int ni = 0; ni < 8; ni++)
#pragma unroll
            for (int q = 0; q < 4; q++) c[mi][ni][q] = 0.f;

    auto load_stage = [&](int stg, int kt) {
        const int KC = BK / 4;
#pragma unroll
        for (int ch = t; ch < 32 * BK; ch += 256) {
            int row = ch / KC;
            int kq = (ch % KC) * 4;
            cp16(asu + (stg * ASZ + row * SA + kq) * 4, A + (size_t)(bm + row) * K + kt + kq);
            cp16(bsu + (stg * BSZ + row * SA + kq) * 4, A + (size_t)(bn + row) * K + kt + kq);
        }
        cp_commit();
    };

    int T = K / BK;
    load_stage(0, 0);
    load_stage(1, BK);

    for (int kt = 0; kt < T; kt++) {
        cp_wait1();
        __syncthreads();
        int stg = kt % S;
        if (kt + S - 1 < T) load_stage((kt + S - 1) % S, (kt + S - 1) * BK);

        const float* Ast = As + stg * ASZ;
        const float* Bst = Bs + stg * BSZ;
#pragma unroll
        for (int ks = 0; ks < BK; ks += 8) {
            unsigned a[2][4], bf[8][2];
#pragma unroll
            for (int mi = 0; mi < 2; mi++) {
                int rb = wm + mi * 16;
                a[mi][0] = __float_as_uint(Ast[(rb + g) * SA + ks + tig]);
                a[mi][1] = __float_as_uint(Ast[(rb + g + 8) * SA + ks + tig]);
                a[mi][2] = __float_as_uint(Ast[(rb + g) * SA + ks + tig + 4]);
                a[mi][3] = __float_as_uint(Ast[(rb + g + 8) * SA + ks + tig + 4]);
            }
#pragma unroll
            for (int ni = 0; ni < 8; ni++) {
                int cb = wn + ni * 8 + g;
                bf[ni][0] = __float_as_uint(Bst[cb * SA + ks + tig]);
                bf[ni][1] = __float_as_uint(Bst[cb * SA + ks + tig + 4]);
            }
#pragma unroll
            for (int mi = 0; mi < 2; mi++)
#pragma unroll
                for (int ni = 0; ni < 8; ni++)
                    mma_tf32(c[mi][ni], a[mi], bf[ni]);
        }
    }

    // epilogue: threshold test in registers, emit sparse candidates (both orientations)
#pragma unroll
    for (int mi = 0; mi < 2; mi++) {
        int row = bm + wm + mi * 16 + g;
        float rni0 = rn[row], rni8 = rn[row + 8];
#pragma unroll
        for (int ni = 0; ni < 8; ni++) {
            int col = bn + wn + ni * 8 + tig * 2;
            float rcj0 = rn[col], rcj1 = rn[col + 1];
            float v0 = c[mi][ni][0], v1 = c[mi][ni][1];
            float v2 = c[mi][ni][2], v3 = c[mi][ni][3];
            cand_emit(row,     col,     (v0 * rni0) * rcj0);
            cand_emit(row,     col + 1, (v1 * rni0) * rcj1);
            cand_emit(row + 8, col,     (v2 * rni8) * rcj0);
            cand_emit(row + 8, col + 1, (v3 * rni8) * rcj1);
            if (!diag) {
                cand_emit(col,     row,     (v0 * rcj0) * rni0);
                cand_emit(col + 1, row,     (v1 * rcj1) * rni0);
                cand_emit(col,     row + 8, (v2 * rcj0) * rni8);
                cand_emit(col + 1, row + 8, (v3 * rcj1) * rni8);
            }
        }
    }
}

#define SMEM_NT  (3 * (128 * 36 + 128 * 36) * 4)          // 110592
#define SMEM_NN  (3 * (128 * 36 + 32 * 68) * 4)           // 81408

// ---------------- row norms of a1 (+ zero candidate counters) ----------------
__global__ void rnorm_a_kernel(const float* __restrict__ X) {
    __shared__ float red[128];
    int i = blockIdx.x, t = threadIdx.x;
    float s = 0.f;
    for (int j = t; j < HC; j += 128) {
        float v = X[(size_t)i * HC + j];
        s += v * v;
    }
    red[t] = s;
    __syncthreads();
    for (int w = 64; w > 0; w >>= 1) {
        if (t < w) red[t] += red[t + w];
        __syncthreads();
    }
    if (t == 0) {
        g_rnorm[i] = rsqrtf(fmaxf(red[0], 1e-16f));
        g_cand_cnt[i] = 0;
    }
}

// ---------------- softmax over candidate list + gather (exact) ----------------
// Resets counters for the next round; optionally tf32-rounds outputs and emits row rnorm.
__global__ __launch_bounds__(256)
void cand_gather_kernel(const float* __restrict__ V, const int* __restrict__ map,
                        float* __restrict__ out, int vd, int round_out,
                        float* __restrict__ rn_out) {
    __shared__ float sred[256];
    int i = blockIdx.x;
    int t = threadIdx.x;
    int cnt = g_cand_cnt[i];
    __syncthreads();
    if (t == 0) g_cand_cnt[i] = 0;   // ready for next round's emission

    int nq = vd >> 8;
    float acc[8];
#pragma unroll
    for (int q = 0; q < 8; q++) acc[q] = 0.f;

    if (cnt > 0) {
        const int* ci  = g_cand_idx + (size_t)i * N_CLS;
        const float* cv = g_cand_val + (size_t)i * N_CLS;
        float m = -1e30f;
        for (int s = 0; s < cnt; s++) m = fmaxf(m, cv[s]);
        float sum = 0.f;
        for (int s = 0; s < cnt; s++) sum += expf((cv[s] - m) * TSOFT);
        float invS = 1.0f / sum;
        for (int s = 0; s < cnt; s++) {
            int j = ci[s];
            float w = expf((cv[s] - m) * TSOFT) * invS;
            int src = map ? map[j] : j;
            const float* vr = V + (size_t)src * vd;
#pragma unroll
            for (int q = 0; q < 8; q++)
                if (q < nq) acc[q] += w * vr[t + q * 256];
        }
    } else {
        // uniform fallback (reference: all-masked row -> uniform softmax); needs no D
        float w = 1.0f / (float)N_CLS;
        for (int j = 0; j < N_CLS; j++) {
            int src = map ? map[j] : j;
            const float* vr = V + (size_t)src * vd;
#pragma unroll
            for (int q = 0; q < 8; q++)
                if (q < nq) acc[q] += w * vr[t + q * 256];
        }
    }

    float o[8];
#pragma unroll
    for (int q = 0; q < 8; q++)
        if (q < nq) {
            o[q] = round_out ? f2tf(acc[q]) : acc[q];
            out[(size_t)i * vd + t + q * 256] = o[q];
        }

    if (rn_out) {
        float ss = 0.f;
#pragma unroll
        for (int q = 0; q < 8; q++)
            if (q < nq) ss += o[q] * o[q];
        sred[t] = ss;
        __syncthreads();
        for (int w = 128; w > 0; w >>= 1) {
            if (t < w) sred[t] += sred[t + w];
            __syncthreads();
        }
        if (t == 0) rn_out[i] = rsqrtf(fmaxf(sred[0], 1e-16f));
    }
}

// ---------------- launch ----------------
extern "C" void kernel_launch(void* const* d_in, const int* in_sizes, int n_in,
                              void* d_out, int out_size) {
    const float* image      = (const float*)d_in[0];
    const float* attributes = (const float*)d_in[1];
    const int*   labels     = (const int*)d_in[2];
    const int*   tpl        = (const int*)d_in[3];
    const float* ga         = (const float*)d_in[4];
    const float* gv         = (const float*)d_in[5];
    float* out = (float*)d_out;

    float *a1p, *a2p, *b2p, *rnp, *prp, *attrp, *gap, *gvp;
    cudaGetSymbolAddress((void**)&a1p, g_a1);
    cudaGetSymbolAddress((void**)&a2p, g_a2);
    cudaGetSymbolAddress((void**)&b2p, g_b2);
    cudaGetSymbolAddress((void**)&rnp, g_rnorm);
    cudaGetSymbolAddress((void**)&prp, g_protos);
    cudaGetSymbolAddress((void**)&attrp, g_attr_tf);
    cudaGetSymbolAddress((void**)&gap, g_ga_tf);
    cudaGetSymbolAddress((void**)&gvp, g_gv_tf);

    static cudaStream_t s_proto = nullptr;
    static cudaEvent_t ev_fork = nullptr, ev_proto = nullptr;
    if (!s_proto) {
        cudaStreamCreateWithFlags(&s_proto, cudaStreamNonBlocking);
        cudaEventCreateWithFlags(&ev_fork, cudaEventDisableTiming);
        cudaEventCreateWithFlags(&ev_proto, cudaEventDisableTiming);
        cudaFuncSetAttribute(gemm_nt_cand,
                             cudaFuncAttributeMaxDynamicSharedMemorySize, SMEM_NT);
        cudaFuncSetAttribute(gemm_nn_dual,
                             cudaFuncAttributeMaxDynamicSharedMemorySize, SMEM_NN);
    }

    const int NTRI = (N_CLS / 128) * (N_CLS / 128 + 1) / 2;  // 136

    // ---- fork proto chain ----
    cudaEventRecord(ev_fork, 0);
    cudaStreamWaitEvent(s_proto, ev_fork, 0);

    countscan_kernel<<<1, 1024, 0, s_proto>>>(labels);
    scatter_kernel<<<N_IMG / 256, 256, 0, s_proto>>>(labels);
    proto_kernel<<<PROTO_GRID, 256, 0, s_proto>>>(image);
    cudaEventRecord(ev_proto, s_proto);

    // ---- attention critical path (main stream) ----
    round_all_kernel<<<(A4 + 2 * G4 + 255) / 256, 256>>>(attributes, ga, gv);

    // z=0: a1 = attr@ga (tf32-rounded); z=1: b2 = attr@gv
    gemm_nn_dual<<<dim3(HC / 64, N_CLS / 128, 2), 256, SMEM_NN>>>(
        attrp, gap, gvp, a1p, b2p, N_CLS, HC, ATT_D);

    // rn1 from a1 rows (+ zero candidate counters)
    rnorm_a_kernel<<<N_CLS, 128>>>(a1p);

    // NT Gram of a1 -> sparse candidates (no D materialization)
    gemm_nt_cand<<<NTRI, 256, SMEM_NT>>>(a1p, rnp, N_CLS, HC);

    // a2 = softmax(cands) @ b2, tf32-rounded; rn2 emitted; counters re-zeroed
    cand_gather_kernel<<<N_CLS, 256>>>(b2p, nullptr, a2p, HC, 1, rnp);

    // NT Gram of a2 -> candidates round 2
    gemm_nt_cand<<<NTRI, 256, SMEM_NT>>>(a2p, rnp, N_CLS, HC);

    // join proto; final gather into out
    cudaStreamWaitEvent(0, ev_proto, 0);
    cand_gather_kernel<<<N_CLS, 256>>>(prp, tpl, out, IMG_D, 0, nullptr);
}

// round 16
// speedup vs baseline: 1.0455x; 1.0455x over previous
#include <cuda_runtime.h>
#include <math.h>

#define N_IMG   65536
#define IMG_D   2048
#define N_CLS   2048
#define ATT_D   1024
#define HC      512
#define TSOFT   10.0f
#define THRESH  0.17364817766693041f
#define PROTO_GRID 296

// ---------------- scratch (static device memory; no allocation) ----------------
__device__ float g_a1[N_CLS * HC];
__device__ float g_a2[N_CLS * HC];
__device__ float g_b2[N_CLS * HC];
__device__ float g_rnorm[N_CLS];
__device__ float g_rowsq[N_CLS];      // zero-init; cleared by final gather each replay
__device__ float g_protos[N_CLS * IMG_D];
__device__ int   g_count[N_CLS];
__device__ int   g_offset[N_CLS];
__device__ int   g_cursor[N_CLS];
__device__ int   g_perm[N_IMG];
// candidate lists: a full row fits -> overflow impossible
__device__ int   g_cand_cnt[N_CLS];   // zero-init; self-reset by gathers
__device__ int   g_cand_idx[N_CLS * N_CLS];
__device__ float g_cand_val[N_CLS * N_CLS];

__device__ __forceinline__ float f2tf(float x) {
    unsigned r;
    asm("cvt.rna.tf32.f32 %0, %1;" : "=r"(r) : "f"(x));
    return __uint_as_float(r);
}
__device__ __forceinline__ unsigned f2tfu(float x) {
    unsigned r;
    asm("cvt.rna.tf32.f32 %0, %1;" : "=r"(r) : "f"(x));
    return r;
}

// ---------------- segment mean chain (side stream) ----------------
__global__ void countscan_kernel(const int* __restrict__ labels) {
    __shared__ int cnt[N_CLS];
    __shared__ int b[1024];
    int t = threadIdx.x;
    cnt[t] = 0; cnt[t + 1024] = 0;
    __syncthreads();
    for (int i = t; i < N_IMG; i += 1024) atomicAdd(&cnt[labels[i]], 1);
    __syncthreads();
    b[t] = cnt[2 * t] + cnt[2 * t + 1];
    __syncthreads();
    for (int off = 1; off < 1024; off <<= 1) {
        int v = (t >= off) ? b[t - off] : 0;
        __syncthreads();
        b[t] += v;
        __syncthreads();
    }
    int excl = (t == 0) ? 0 : b[t - 1];
    g_count[2 * t]      = cnt[2 * t];
    g_count[2 * t + 1]  = cnt[2 * t + 1];
    g_offset[2 * t]     = excl;
    g_offset[2 * t + 1] = excl + cnt[2 * t];
    g_cursor[2 * t]     = excl;
    g_cursor[2 * t + 1] = excl + cnt[2 * t];
}

__global__ void scatter_kernel(const int* __restrict__ labels) {
    int i = blockIdx.x * blockDim.x + threadIdx.x;
    if (i < N_IMG) {
        int l = labels[i];
        int pos = atomicAdd(&g_cursor[l], 1);
        g_perm[pos] = i;
    }
}

// persistent proto: grid-stride over 4096 (class, half) items
__global__ void proto_kernel(const float* __restrict__ imgs) {
    for (int w = blockIdx.x; w < N_CLS * 2; w += PROTO_GRID) {
        int c = w >> 1;
        int col = (w & 1) * 1024 + threadIdx.x * 4;
        int cnt  = g_count[c];
        int base = g_offset[c];
        float4 acc = make_float4(0.f, 0.f, 0.f, 0.f);
        int r = 0;
        for (; r + 8 <= cnt; r += 8) {
            float4 v[8];
#pragma unroll
            for (int u = 0; u < 8; u++) {
                int idx = g_perm[base + r + u];
                v[u] = __ldcs((const float4*)(imgs + (size_t)idx * IMG_D + col));
            }
#pragma unroll
            for (int u = 0; u < 8; u++) {
                acc.x += v[u].x; acc.y += v[u].y; acc.z += v[u].z; acc.w += v[u].w;
            }
        }
        for (; r < cnt; r++) {
            int idx = g_perm[base + r];
            float4 v0 = __ldcs((const float4*)(imgs + (size_t)idx * IMG_D + col));
            acc.x += v0.x; acc.y += v0.y; acc.z += v0.z; acc.w += v0.w;
        }
        float inv = (cnt > 0) ? (1.0f / (float)cnt) : 0.0f;
        acc.x *= inv; acc.y *= inv; acc.z *= inv; acc.w *= inv;
        *(float4*)(g_protos + (size_t)c * IMG_D + col) = acc;
    }
}

// ---------------- MMA / cp.async primitives ----------------
__device__ __forceinline__ void mma_tf32(float* c, const unsigned* a, const unsigned* b) {
    asm volatile(
        "mma.sync.aligned.m16n8k8.row.col.f32.tf32.tf32.f32 "
        "{%0,%1,%2,%3}, {%4,%5,%6,%7}, {%8,%9}, {%0,%1,%2,%3};"
        : "+f"(c[0]), "+f"(c[1]), "+f"(c[2]), "+f"(c[3])
        : "r"(a[0]), "r"(a[1]), "r"(a[2]), "r"(a[3]), "r"(b[0]), "r"(b[1]));
}
__device__ __forceinline__ void cp16(unsigned dst, const float* src) {
    asm volatile("cp.async.cg.shared.global [%0], [%1], 16;" :: "r"(dst), "l"(src));
}
__device__ __forceinline__ void cp_commit() { asm volatile("cp.async.commit_group;"); }
__device__ __forceinline__ void cp_wait1()  { asm volatile("cp.async.wait_group 1;"); }

// ---------------- dual NN GEMM on RAW fp32 inputs (tf32 cvt on fragments) ----------------
// z=0: a1 = attr@ga -> tf32-rounded store + per-row sum-of-squares atomics
// z=1: b2 = attr@gv -> plain fp32 store
__global__ __launch_bounds__(256)
void gemm_nn_dual(const float* __restrict__ A, const float* __restrict__ B0,
                  const float* __restrict__ B1, float* __restrict__ C0, float* __restrict__ C1,
                  int M, int N, int K) {
    const int S = 3, BK = 32, BN = 64;
    const int SA = 36, SBN = 68;
    const int ASZ = 128 * SA, BSZ = BK * SBN;

    const float* B = (blockIdx.z == 0) ? B0 : B1;
    float* C       = (blockIdx.z == 0) ? C0 : C1;
    bool z0        = (blockIdx.z == 0);

    extern __shared__ float sm[];
    float* As = sm;
    float* Bs = sm + S * ASZ;
    unsigned asu = (unsigned)__cvta_generic_to_shared(As);
    unsigned bsu = (unsigned)__cvta_generic_to_shared(Bs);

    int t = threadIdx.x;
    int warp = t >> 5, lane = t & 31, g = lane >> 2, tig = lane & 3;
    int bm = blockIdx.y * 128, bn = blockIdx.x * BN;
    int wm = (warp >> 1) * 32, wn = (warp & 1) * (BN / 2);

    float c[2][4][4];
#pragma unroll
    for (int mi = 0; mi < 2; mi++)
#pragma unroll
        for (int ni = 0; ni < 4; ni++)
#pragma unroll
            for (int q = 0; q < 4; q++) c[mi][ni][q] = 0.f;

    auto load_stage = [&](int stg, int kt) {
        const int KC = BK / 4;
#pragma unroll
        for (int ch = t; ch < 32 * BK; ch += 256) {
            int row = ch / KC;
            int kq = (ch % KC) * 4;
            cp16(asu + (stg * ASZ + row * SA + kq) * 4, A + (size_t)(bm + row) * K + kt + kq);
        }
        const int NC = BN / 4;
#pragma unroll
        for (int ch = t; ch < (BK * BN) / 4; ch += 256) {
            int krow = ch / NC;
            int nq = (ch % NC) * 4;
            cp16(bsu + (stg * BSZ + krow * SBN + nq) * 4, B + (size_t)(kt + krow) * N + bn + nq);
        }
        cp_commit();
    };

    int T = K / BK;
    load_stage(0, 0);
    load_stage(1, BK);

    for (int kt = 0; kt < T; kt++) {
        cp_wait1();
        __syncthreads();
        int stg = kt % S;
        if (kt + S - 1 < T) load_stage((kt + S - 1) % S, (kt + S - 1) * BK);

        const float* Ast = As + stg * ASZ;
        const float* Bst = Bs + stg * BSZ;
#pragma unroll
        for (int ks = 0; ks < BK; ks += 8) {
            unsigned a[2][4], bf[4][2];
#pragma unroll
            for (int mi = 0; mi < 2; mi++) {
                int rb = wm + mi * 16;
                a[mi][0] = f2tfu(Ast[(rb + g) * SA + ks + tig]);
                a[mi][1] = f2tfu(Ast[(rb + g + 8) * SA + ks + tig]);
                a[mi][2] = f2tfu(Ast[(rb + g) * SA + ks + tig + 4]);
                a[mi][3] = f2tfu(Ast[(rb + g + 8) * SA + ks + tig + 4]);
            }
#pragma unroll
            for (int ni = 0; ni < 4; ni++) {
                int cb = wn + ni * 8 + g;
                bf[ni][0] = f2tfu(Bst[(ks + tig) * SBN + cb]);
                bf[ni][1] = f2tfu(Bst[(ks + tig + 4) * SBN + cb]);
            }
#pragma unroll
            for (int mi = 0; mi < 2; mi++)
#pragma unroll
                for (int ni = 0; ni < 4; ni++)
                    mma_tf32(c[mi][ni], a[mi], bf[ni]);
        }
    }

#pragma unroll
    for (int mi = 0; mi < 2; mi++) {
        int row = bm + wm + mi * 16 + g;
        float ss0 = 0.f, ss8 = 0.f;
#pragma unroll
        for (int ni = 0; ni < 4; ni++) {
            int col = bn + wn + ni * 8 + tig * 2;
            float v0 = c[mi][ni][0], v1 = c[mi][ni][1];
            float v2 = c[mi][ni][2], v3 = c[mi][ni][3];
            if (z0) {
                v0 = f2tf(v0); v1 = f2tf(v1); v2 = f2tf(v2); v3 = f2tf(v3);
                ss0 += v0 * v0 + v1 * v1;
                ss8 += v2 * v2 + v3 * v3;
            }
            *(float2*)(C + (size_t)row * N + col)       = make_float2(v0, v1);
            *(float2*)(C + (size_t)(row + 8) * N + col) = make_float2(v2, v3);
        }
        if (z0) {
            atomicAdd(&g_rowsq[row], ss0);
            atomicAdd(&g_rowsq[row + 8], ss8);
        }
    }
}

// ---------------- NT Gram + in-register threshold -> candidate lists ----------------
__device__ __forceinline__ void cand_emit(int i, int j, float vs) {
    if (vs > THRESH) {
        int p = atomicAdd(&g_cand_cnt[i], 1);
        g_cand_idx[(size_t)i * N_CLS + p] = j;
        g_cand_val[(size_t)i * N_CLS + p] = vs;
    }
}

// rn_is_sq: rnsrc holds sum-of-squares (round 1, from dual-GEMM atomics); else direct rn.
__global__ __launch_bounds__(256)
void gemm_nt_cand(const float* __restrict__ A, const float* __restrict__ rnsrc,
                  int rn_is_sq, int N, int K) {
    const int S = 3, BK = 32, BN = 128;
    const int SA = 36;
    const int ASZ = 128 * SA, BSZ = BN * SA;

    extern __shared__ float sm[];
    float* As = sm;
    float* Bs = sm + S * ASZ;
    __shared__ float rnA[128], rnB[128];
    unsigned asu = (unsigned)__cvta_generic_to_shared(As);
    unsigned bsu = (unsigned)__cvta_generic_to_shared(Bs);

    int t = threadIdx.x;
    int warp = t >> 5, lane = t & 31, g = lane >> 2, tig = lane & 3;

    int bi = blockIdx.x, r = 0, rowlen = N / 128;
    while (bi >= rowlen) { bi -= rowlen; r++; rowlen--; }
    int bm = r * 128;
    int bn = (r + bi) * 128;
    bool diag = (bm == bn);

    // load per-row/col rnorms into smem (convert from sum-of-squares if needed)
    if (t < 128) {
        float v = rnsrc[bm + t];
        rnA[t] = rn_is_sq ? rsqrtf(fmaxf(v, 1e-16f)) : v;
    } else {
        float v = rnsrc[bn + t - 128];
        rnB[t - 128] = rn_is_sq ? rsqrtf(fmaxf(v, 1e-16f)) : v;
    }

    int wm = (warp >> 1) * 32, wn = (warp & 1) * 64;

    float c[2][8][4];
#pragma unroll
    for (int mi = 0; mi < 2; mi++)
#pragma unroll
        for (int ni = 0; ni < 8; ni++)
#pragma unroll
            for (int q = 0; q < 4; q++) c[mi][ni][q] = 0.f;

    auto load_stage = [&](int stg, int kt) {
        const int KC = BK / 4;
#pragma unroll
        for (int ch = t; ch < 32 * BK; ch += 256) {
            int row = ch / KC;
            int kq = (ch % KC) * 4;
            cp16(asu + (stg * ASZ + row * SA + kq) * 4, A + (size_t)(bm + row) * K + kt + kq);
            cp16(bsu + (stg * BSZ + row * SA + kq) * 4, A + (size_t)(bn + row) * K + kt + kq);
        }
        cp_commit();
    };

    int T = K / BK;
    load_stage(0, 0);
    load_stage(1, BK);

    for (int kt = 0; kt < T; kt++) {
        cp_wait1();
        __syncthreads();
        int stg = kt % S;
        if (kt + S - 1 < T) load_stage((kt + S - 1) % S, (kt + S - 1) * BK);

        const float* Ast = As + stg * ASZ;
        const float* Bst = Bs + stg * BSZ;
#pragma unroll
        for (int ks = 0; ks < BK; ks += 8) {
            unsigned a[2][4], bf[8][2];
#pragma unroll
            for (int mi = 0; mi < 2; mi++) {
                int rb = wm + mi * 16;
                a[mi][0] = __float_as_uint(Ast[(rb + g) * SA + ks + tig]);
                a[mi][1] = __float_as_uint(Ast[(rb + g + 8) * SA + ks + tig]);
                a[mi][2] = __float_as_uint(Ast[(rb + g) * SA + ks + tig + 4]);
                a[mi][3] = __float_as_uint(Ast[(rb + g + 8) * SA + ks + tig + 4]);
            }
#pragma unroll
            for (int ni = 0; ni < 8; ni++) {
                int cb = wn + ni * 8 + g;
                bf[ni][0] = __float_as_uint(Bst[cb * SA + ks + tig]);
                bf[ni][1] = __float_as_uint(Bst[cb * SA + ks + tig + 4]);
            }
#pragma unroll
            for (int mi = 0; mi < 2; mi++)
#pragma unroll
                for (int ni = 0; ni < 8; ni++)
                    mma_tf32(c[mi][ni], a[mi], bf[ni]);
        }
    }

#pragma unroll
    for (int mi = 0; mi < 2; mi++) {
        int lrow = wm + mi * 16 + g;
        int row = bm + lrow;
        float rni0 = rnA[lrow], rni8 = rnA[lrow + 8];
#pragma unroll
        for (int ni = 0; ni < 8; ni++) {
            int lcol = wn + ni * 8 + tig * 2;
            int col = bn + lcol;
            float rcj0 = rnB[lcol], rcj1 = rnB[lcol + 1];
            float v0 = c[mi][ni][0], v1 = c[mi][ni][1];
            float v2 = c[mi][ni][2], v3 = c[mi][ni][3];
            cand_emit(row,     col,     (v0 * rni0) * rcj0);
            cand_emit(row,     col + 1, (v1 * rni0) * rcj1);
            cand_emit(row + 8, col,     (v2 * rni8) * rcj0);
            cand_emit(row + 8, col + 1, (v3 * rni8) * rcj1);
            if (!diag) {
                cand_emit(col,     row,     (v0 * rcj0) * rni0);
                cand_emit(col + 1, row,     (v1 * rcj1) * rni0);
                cand_emit(col,     row + 8, (v2 * rcj0) * rni8);
                cand_emit(col + 1, row + 8, (v3 * rcj1) * rni8);
            }
        }
    }
}

#define SMEM_NT  (3 * (128 * 36 + 128 * 36) * 4)          // 110592
#define SMEM_NN  (3 * (128 * 36 + 32 * 68) * 4)           // 81408

// ---------------- softmax over candidate list + gather (exact) ----------------
__global__ __launch_bounds__(256)
void cand_gather_kernel(const float* __restrict__ V, const int* __restrict__ map,
                        float* __restrict__ out, int vd, int round_out,
                        float* __restrict__ rn_out, int clear_sq) {
    __shared__ float sred[256];
    int i = blockIdx.x;
    int t = threadIdx.x;
    int cnt = g_cand_cnt[i];
    __syncthreads();
    if (t == 0) {
        g_cand_cnt[i] = 0;                 // ready for next emission
        if (clear_sq) g_rowsq[i] = 0.f;    // ready for next replay's dual-GEMM
    }

    int nq = vd >> 8;
    float acc[8];
#pragma unroll
    for (int q = 0; q < 8; q++) acc[q] = 0.f;

    if (cnt > 0) {
        const int* ci   = g_cand_idx + (size_t)i * N_CLS;
        const float* cv = g_cand_val + (size_t)i * N_CLS;
        float m = -1e30f;
        for (int s = 0; s < cnt; s++) m = fmaxf(m, cv[s]);
        float sum = 0.f;
        for (int s = 0; s < cnt; s++) sum += expf((cv[s] - m) * TSOFT);
        float invS = 1.0f / sum;
        for (int s = 0; s < cnt; s++) {
            int j = ci[s];
            float w = expf((cv[s] - m) * TSOFT) * invS;
            int src = map ? map[j] : j;
            const float* vr = V + (size_t)src * vd;
#pragma unroll
            for (int q = 0; q < 8; q++)
                if (q < nq) acc[q] += w * vr[t + q * 256];
        }
    } else {
        // all-masked row -> uniform softmax (reference semantics); unreachable in practice
        float w = 1.0f / (float)N_CLS;
        for (int j = 0; j < N_CLS; j++) {
            int src = map ? map[j] : j;
            const float* vr = V + (size_t)src * vd;
#pragma unroll
            for (int q = 0; q < 8; q++)
                if (q < nq) acc[q] += w * vr[t + q * 256];
        }
    }

    float o[8];
#pragma unroll
    for (int q = 0; q < 8; q++)
        if (q < nq) {
            o[q] = round_out ? f2tf(acc[q]) : acc[q];
            out[(size_t)i * vd + t + q * 256] = o[q];
        }

    if (rn_out) {
        float ss = 0.f;
#pragma unroll
        for (int q = 0; q < 8; q++)
            if (q < nq) ss += o[q] * o[q];
        sred[t] = ss;
        __syncthreads();
        for (int w = 128; w > 0; w >>= 1) {
            if (t < w) sred[t] += sred[t + w];
            __syncthreads();
        }
        if (t == 0) rn_out[i] = rsqrtf(fmaxf(sred[0], 1e-16f));
    }
}

// ---------------- launch ----------------
extern "C" void kernel_launch(void* const* d_in, const int* in_sizes, int n_in,
                              void* d_out, int out_size) {
    const float* image      = (const float*)d_in[0];
    const float* attributes = (const float*)d_in[1];
    const int*   labels     = (const int*)d_in[2];
    const int*   tpl        = (const int*)d_in[3];
    const float* ga         = (const float*)d_in[4];
    const float* gv         = (const float*)d_in[5];
    float* out = (float*)d_out;

    float *a1p, *a2p, *b2p, *rnp, *rsqp, *prp;
    cudaGetSymbolAddress((void**)&a1p, g_a1);
    cudaGetSymbolAddress((void**)&a2p, g_a2);
    cudaGetSymbolAddress((void**)&b2p, g_b2);
    cudaGetSymbolAddress((void**)&rnp, g_rnorm);
    cudaGetSymbolAddress((void**)&rsqp, g_rowsq);
    cudaGetSymbolAddress((void**)&prp, g_protos);

    static cudaStream_t s_proto = nullptr;
    static cudaEvent_t ev_fork = nullptr, ev_proto = nullptr;
    if (!s_proto) {
        cudaStreamCreateWithFlags(&s_proto, cudaStreamNonBlocking);
        cudaEventCreateWithFlags(&ev_fork, cudaEventDisableTiming);
        cudaEventCreateWithFlags(&ev_proto, cudaEventDisableTiming);
        cudaFuncSetAttribute(gemm_nt_cand,
                             cudaFuncAttributeMaxDynamicSharedMemorySize, SMEM_NT);
        cudaFuncSetAttribute(gemm_nn_dual,
                             cudaFuncAttributeMaxDynamicSharedMemorySize, SMEM_NN);
    }

    const int NTRI = (N_CLS / 128) * (N_CLS / 128 + 1) / 2;  // 136

    // ---- fork proto chain ----
    cudaEventRecord(ev_fork, 0);
    cudaStreamWaitEvent(s_proto, ev_fork, 0);

    countscan_kernel<<<1, 1024, 0, s_proto>>>(labels);
    scatter_kernel<<<N_IMG / 256, 256, 0, s_proto>>>(labels);
    proto_kernel<<<PROTO_GRID, 256, 0, s_proto>>>(image);
    cudaEventRecord(ev_proto, s_proto);

    // ---- attention critical path (main stream): 5 nodes ----
    // z=0: a1 = attr@ga (tf32 out + rowsq atomics); z=1: b2 = attr@gv
    gemm_nn_dual<<<dim3(HC / 64, N_CLS / 128, 2), 256, SMEM_NN>>>(
        attributes, ga, gv, a1p, b2p, N_CLS, HC, ATT_D);

    // NT Gram of a1 -> candidates (rn from rowsq)
    gemm_nt_cand<<<NTRI, 256, SMEM_NT>>>(a1p, rsqp, 1, N_CLS, HC);

    // a2 = softmax(cands) @ b2 (tf32-rounded out); rn2 emitted; counters reset
    cand_gather_kernel<<<N_CLS, 256>>>(b2p, nullptr, a2p, HC, 1, rnp, 0);

    // NT Gram of a2 -> candidates round 2 (rn direct)
    gemm_nt_cand<<<NTRI, 256, SMEM_NT>>>(a2p, rnp, 0, N_CLS, HC);

    // join proto; final gather (also clears rowsq for next replay)
    cudaStreamWaitEvent(0, ev_proto, 0);
    cand_gather_kernel<<<N_CLS, 256>>>(prp, tpl, out, IMG_D, 0, nullptr, 1);
}

// round 17
// speedup vs baseline: 1.0664x; 1.0200x over previous
#include <cuda_runtime.h>
#include <math.h>

#define N_IMG   65536
#define IMG_D   2048
#define N_CLS   2048
#define ATT_D   1024
#define HC      512
#define TSOFT   10.0f
#define THRESH  0.17364817766693041f
#define PROTO_GRID 296

// ---------------- scratch (static device memory; no allocation) ----------------
__device__ float g_a1[N_CLS * HC];
__device__ float g_a2[N_CLS * HC];
__device__ float g_b2[N_CLS * HC];
__device__ float g_rnorm[N_CLS];
__device__ float g_rowsq[N_CLS];      // zero-init; cleared by final gather each replay
__device__ float g_protos[N_CLS * IMG_D];
__device__ int   g_count[N_CLS];
__device__ int   g_offset[N_CLS];
__device__ int   g_cursor[N_CLS];
__device__ int   g_perm[N_IMG];
// candidate lists: a full row fits -> overflow impossible
__device__ int   g_cand_cnt[N_CLS];   // zero-init; self-reset by gathers
__device__ int   g_cand_idx[N_CLS * N_CLS];
__device__ float g_cand_val[N_CLS * N_CLS];

__device__ __forceinline__ float f2tf(float x) {
    unsigned r;
    asm("cvt.rna.tf32.f32 %0, %1;" : "=r"(r) : "f"(x));
    return __uint_as_float(r);
}

// ---------------- segment mean chain (side stream) ----------------
__global__ void countscan_kernel(const int* __restrict__ labels) {
    __shared__ int cnt[N_CLS];
    __shared__ int b[1024];
    int t = threadIdx.x;
    cnt[t] = 0; cnt[t + 1024] = 0;
    __syncthreads();
    for (int i = t; i < N_IMG; i += 1024) atomicAdd(&cnt[labels[i]], 1);
    __syncthreads();
    b[t] = cnt[2 * t] + cnt[2 * t + 1];
    __syncthreads();
    for (int off = 1; off < 1024; off <<= 1) {
        int v = (t >= off) ? b[t - off] : 0;
        __syncthreads();
        b[t] += v;
        __syncthreads();
    }
    int excl = (t == 0) ? 0 : b[t - 1];
    g_count[2 * t]      = cnt[2 * t];
    g_count[2 * t + 1]  = cnt[2 * t + 1];
    g_offset[2 * t]     = excl;
    g_offset[2 * t + 1] = excl + cnt[2 * t];
    g_cursor[2 * t]     = excl;
    g_cursor[2 * t + 1] = excl + cnt[2 * t];
}

__global__ void scatter_kernel(const int* __restrict__ labels) {
    int i = blockIdx.x * blockDim.x + threadIdx.x;
    if (i < N_IMG) {
        int l = labels[i];
        int pos = atomicAdd(&g_cursor[l], 1);
        g_perm[pos] = i;
    }
}

// persistent proto: grid-stride over 4096 (class, half) items
__global__ void proto_kernel(const float* __restrict__ imgs) {
    for (int w = blockIdx.x; w < N_CLS * 2; w += PROTO_GRID) {
        int c = w >> 1;
        int col = (w & 1) * 1024 + threadIdx.x * 4;
        int cnt  = g_count[c];
        int base = g_offset[c];
        float4 acc = make_float4(0.f, 0.f, 0.f, 0.f);
        int r = 0;
        for (; r + 8 <= cnt; r += 8) {
            float4 v[8];
#pragma unroll
            for (int u = 0; u < 8; u++) {
                int idx = g_perm[base + r + u];
                v[u] = __ldcs((const float4*)(imgs + (size_t)idx * IMG_D + col));
            }
#pragma unroll
            for (int u = 0; u < 8; u++) {
                acc.x += v[u].x; acc.y += v[u].y; acc.z += v[u].z; acc.w += v[u].w;
            }
        }
        for (; r < cnt; r++) {
            int idx = g_perm[base + r];
            float4 v0 = __ldcs((const float4*)(imgs + (size_t)idx * IMG_D + col));
            acc.x += v0.x; acc.y += v0.y; acc.z += v0.z; acc.w += v0.w;
        }
        float inv = (cnt > 0) ? (1.0f / (float)cnt) : 0.0f;
        acc.x *= inv; acc.y *= inv; acc.z *= inv; acc.w *= inv;
        *(float4*)(g_protos + (size_t)c * IMG_D + col) = acc;
    }
}

// ---------------- MMA / cp.async primitives ----------------
__device__ __forceinline__ void mma_tf32(float* c, const unsigned* a, const unsigned* b) {
    asm volatile(
        "mma.sync.aligned.m16n8k8.row.col.f32.tf32.tf32.f32 "
        "{%0,%1,%2,%3}, {%4,%5,%6,%7}, {%8,%9}, {%0,%1,%2,%3};"
        : "+f"(c[0]), "+f"(c[1]), "+f"(c[2]), "+f"(c[3])
        : "r"(a[0]), "r"(a[1]), "r"(a[2]), "r"(a[3]), "r"(b[0]), "r"(b[1]));
}
__device__ __forceinline__ void cp16(unsigned dst, const float* src) {
    asm volatile("cp.async.cg.shared.global [%0], [%1], 16;" :: "r"(dst), "l"(src));
}
__device__ __forceinline__ void cp_commit() { asm volatile("cp.async.commit_group;"); }
__device__ __forceinline__ void cp_wait1()  { asm volatile("cp.async.wait_group 1;"); }

// ---------------- dual NN GEMM on RAW fp32 inputs (HW tf32 truncation in MMA) ----------------
// z=0: a1 = attr@ga -> tf32-rounded store + per-row sum-of-squares atomics
// z=1: b2 = attr@gv -> plain fp32 store
__global__ __launch_bounds__(256)
void gemm_nn_dual(const float* __restrict__ A, const float* __restrict__ B0,
                  const float* __restrict__ B1, float* __restrict__ C0, float* __restrict__ C1,
                  int M, int N, int K) {
    const int S = 3, BK = 32, BN = 64;
    const int SA = 36, SBN = 68;
    const int ASZ = 128 * SA, BSZ = BK * SBN;

    const float* B = (blockIdx.z == 0) ? B0 : B1;
    float* C       = (blockIdx.z == 0) ? C0 : C1;
    bool z0        = (blockIdx.z == 0);

    extern __shared__ float sm[];
    float* As = sm;
    float* Bs = sm + S * ASZ;
    unsigned asu = (unsigned)__cvta_generic_to_shared(As);
    unsigned bsu = (unsigned)__cvta_generic_to_shared(Bs);

    int t = threadIdx.x;
    int warp = t >> 5, lane = t & 31, g = lane >> 2, tig = lane & 3;
    int bm = blockIdx.y * 128, bn = blockIdx.x * BN;
    int wm = (warp >> 1) * 32, wn = (warp & 1) * (BN / 2);

    float c[2][4][4];
#pragma unroll
    for (int mi = 0; mi < 2; mi++)
#pragma unroll
        for (int ni = 0; ni < 4; ni++)
#pragma unroll
            for (int q = 0; q < 4; q++) c[mi][ni][q] = 0.f;

    auto load_stage = [&](int stg, int kt) {
        const int KC = BK / 4;
#pragma unroll
        for (int ch = t; ch < 32 * BK; ch += 256) {
            int row = ch / KC;
            int kq = (ch % KC) * 4;
            cp16(asu + (stg * ASZ + row * SA + kq) * 4, A + (size_t)(bm + row) * K + kt + kq);
        }
        const int NC = BN / 4;
#pragma unroll
        for (int ch = t; ch < (BK * BN) / 4; ch += 256) {
            int krow = ch / NC;
            int nq = (ch % NC) * 4;
            cp16(bsu + (stg * BSZ + krow * SBN + nq) * 4, B + (size_t)(kt + krow) * N + bn + nq);
        }
        cp_commit();
    };

    int T = K / BK;
    load_stage(0, 0);
    load_stage(1, BK);

    for (int kt = 0; kt < T; kt++) {
        cp_wait1();
        __syncthreads();
        int stg = kt % S;
        if (kt + S - 1 < T) load_stage((kt + S - 1) % S, (kt + S - 1) * BK);

        const float* Ast = As + stg * ASZ;
        const float* Bst = Bs + stg * BSZ;
#pragma unroll
        for (int ks = 0; ks < BK; ks += 8) {
            unsigned a[2][4], bf[4][2];
#pragma unroll
            for (int mi = 0; mi < 2; mi++) {
                int rb = wm + mi * 16;
                a[mi][0] = __float_as_uint(Ast[(rb + g) * SA + ks + tig]);
                a[mi][1] = __float_as_uint(Ast[(rb + g + 8) * SA + ks + tig]);
                a[mi][2] = __float_as_uint(Ast[(rb + g) * SA + ks + tig + 4]);
                a[mi][3] = __float_as_uint(Ast[(rb + g + 8) * SA + ks + tig + 4]);
            }
#pragma unroll
            for (int ni = 0; ni < 4; ni++) {
                int cb = wn + ni * 8 + g;
                bf[ni][0] = __float_as_uint(Bst[(ks + tig) * SBN + cb]);
                bf[ni][1] = __float_as_uint(Bst[(ks + tig + 4) * SBN + cb]);
            }
#pragma unroll
            for (int mi = 0; mi < 2; mi++)
#pragma unroll
                for (int ni = 0; ni < 4; ni++)
                    mma_tf32(c[mi][ni], a[mi], bf[ni]);
        }
    }

#pragma unroll
    for (int mi = 0; mi < 2; mi++) {
        int row = bm + wm + mi * 16 + g;
        float ss0 = 0.f, ss8 = 0.f;
#pragma unroll
        for (int ni = 0; ni < 4; ni++) {
            int col = bn + wn + ni * 8 + tig * 2;
            float v0 = c[mi][ni][0], v1 = c[mi][ni][1];
            float v2 = c[mi][ni][2], v3 = c[mi][ni][3];
            if (z0) {
                v0 = f2tf(v0); v1 = f2tf(v1); v2 = f2tf(v2); v3 = f2tf(v3);
                ss0 += v0 * v0 + v1 * v1;
                ss8 += v2 * v2 + v3 * v3;
            }
            *(float2*)(C + (size_t)row * N + col)       = make_float2(v0, v1);
            *(float2*)(C + (size_t)(row + 8) * N + col) = make_float2(v2, v3);
        }
        if (z0) {
            atomicAdd(&g_rowsq[row], ss0);
            atomicAdd(&g_rowsq[row + 8], ss8);
        }
    }
}

// ---------------- NT Gram + in-register threshold -> candidate lists ----------------
__device__ __forceinline__ void cand_emit(int i, int j, float vs) {
    if (vs > THRESH) {
        int p = atomicAdd(&g_cand_cnt[i], 1);
        g_cand_idx[(size_t)i * N_CLS + p] = j;
        g_cand_val[(size_t)i * N_CLS + p] = vs;
    }
}

// rn_is_sq: rnsrc holds sum-of-squares (round 1, from dual-GEMM atomics); else direct rn.
__global__ __launch_bounds__(256)
void gemm_nt_cand(const float* __restrict__ A, const float* __restrict__ rnsrc,
                  int rn_is_sq, int N, int K) {
    const int S = 3, BK = 32, BN = 128;
    const int SA = 36;
    const int ASZ = 128 * SA, BSZ = BN * SA;

    extern __shared__ float sm[];
    float* As = sm;
    float* Bs = sm + S * ASZ;
    __shared__ float rnA[128], rnB[128];
    unsigned asu = (unsigned)__cvta_generic_to_shared(As);
    unsigned bsu = (unsigned)__cvta_generic_to_shared(Bs);

    int t = threadIdx.x;
    int warp = t >> 5, lane = t & 31, g = lane >> 2, tig = lane & 3;

    int bi = blockIdx.x, r = 0, rowlen = N / 128;
    while (bi >= rowlen) { bi -= rowlen; r++; rowlen--; }
    int bm = r * 128;
    int bn = (r + bi) * 128;
    bool diag = (bm == bn);

    if (t < 128) {
        float v = rnsrc[bm + t];
        rnA[t] = rn_is_sq ? rsqrtf(fmaxf(v, 1e-16f)) : v;
    } else {
        float v = rnsrc[bn + t - 128];
        rnB[t - 128] = rn_is_sq ? rsqrtf(fmaxf(v, 1e-16f)) : v;
    }

    int wm = (warp >> 1) * 32, wn = (warp & 1) * 64;

    float c[2][8][4];
#pragma unroll
    for (int mi = 0; mi < 2; mi++)
#pragma unroll
        for (int ni = 0; ni < 8; ni++)
#pragma unroll
            for (int q = 0; q < 4; q++) c[mi][ni][q] = 0.f;

    auto load_stage = [&](int stg, int kt) {
        const int KC = BK / 4;
#pragma unroll
        for (int ch = t; ch < 32 * BK; ch += 256) {
            int row = ch / KC;
            int kq = (ch % KC) * 4;
            cp16(asu + (stg * ASZ + row * SA + kq) * 4, A + (size_t)(bm + row) * K + kt + kq);
            cp16(bsu + (stg * BSZ + row * SA + kq) * 4, A + (size_t)(bn + row) * K + kt + kq);
        }
        cp_commit();
    };

    int T = K / BK;
    load_stage(0, 0);
    load_stage(1, BK);

    for (int kt = 0; kt < T; kt++) {
        cp_wait1();
        __syncthreads();
        int stg = kt % S;
        if (kt + S - 1 < T) load_stage((kt + S - 1) % S, (kt + S - 1) * BK);

        const float* Ast = As + stg * ASZ;
        const float* Bst = Bs + stg * BSZ;
#pragma unroll
        for (int ks = 0; ks < BK; ks += 8) {
            unsigned a[2][4], bf[8][2];
#pragma unroll
            for (int mi = 0; mi < 2; mi++) {
                int rb = wm + mi * 16;
                a[mi][0] = __float_as_uint(Ast[(rb + g) * SA + ks + tig]);
                a[mi][1] = __float_as_uint(Ast[(rb + g + 8) * SA + ks + tig]);
                a[mi][2] = __float_as_uint(Ast[(rb + g) * SA + ks + tig + 4]);
                a[mi][3] = __float_as_uint(Ast[(rb + g + 8) * SA + ks + tig + 4]);
            }
#pragma unroll
            for (int ni = 0; ni < 8; ni++) {
                int cb = wn + ni * 8 + g;
                bf[ni][0] = __float_as_uint(Bst[cb * SA + ks + tig]);
                bf[ni][1] = __float_as_uint(Bst[cb * SA + ks + tig + 4]);
            }
#pragma unroll
            for (int mi = 0; mi < 2; mi++)
#pragma unroll
                for (int ni = 0; ni < 8; ni++)
                    mma_tf32(c[mi][ni], a[mi], bf[ni]);
        }
    }

#pragma unroll
    for (int mi = 0; mi < 2; mi++) {
        int lrow = wm + mi * 16 + g;
        int row = bm + lrow;
        float rni0 = rnA[lrow], rni8 = rnA[lrow + 8];
#pragma unroll
        for (int ni = 0; ni < 8; ni++) {
            int lcol = wn + ni * 8 + tig * 2;
            int col = bn + lcol;
            float rcj0 = rnB[lcol], rcj1 = rnB[lcol + 1];
            float v0 = c[mi][ni][0], v1 = c[mi][ni][1];
            float v2 = c[mi][ni][2], v3 = c[mi][ni][3];
            cand_emit(row,     col,     (v0 * rni0) * rcj0);
            cand_emit(row,     col + 1, (v1 * rni0) * rcj1);
            cand_emit(row + 8, col,     (v2 * rni8) * rcj0);
            cand_emit(row + 8, col + 1, (v3 * rni8) * rcj1);
            if (!diag) {
                cand_emit(col,     row,     (v0 * rcj0) * rni0);
                cand_emit(col + 1, row,     (v1 * rcj1) * rni0);
                cand_emit(col,     row + 8, (v2 * rcj0) * rni8);
                cand_emit(col + 1, row + 8, (v3 * rcj1) * rni8);
            }
        }
    }
}

#define SMEM_NT  (3 * (128 * 36 + 128 * 36) * 4)          // 110592
#define SMEM_NN  (3 * (128 * 36 + 32 * 68) * 4)           // 81408

// ---------------- softmax over candidate list + gather (exact) ----------------
__global__ __launch_bounds__(256)
void cand_gather_kernel(const float* __restrict__ V, const int* __restrict__ map,
                        float* __restrict__ out, int vd, int round_out,
                        float* __restrict__ rn_out, int clear_sq) {
    __shared__ float sred[256];
    int i = blockIdx.x;
    int t = threadIdx.x;
    int cnt = g_cand_cnt[i];
    __syncthreads();
    if (t == 0) {
        g_cand_cnt[i] = 0;
        if (clear_sq) g_rowsq[i] = 0.f;
    }

    int nq = vd >> 8;
    float acc[8];
#pragma unroll
    for (int q = 0; q < 8; q++) acc[q] = 0.f;

    if (cnt > 0) {
        const int* ci   = g_cand_idx + (size_t)i * N_CLS;
        const float* cv = g_cand_val + (size_t)i * N_CLS;
        float m = -1e30f;
        for (int s = 0; s < cnt; s++) m = fmaxf(m, cv[s]);
        float sum = 0.f;
        for (int s = 0; s < cnt; s++) sum += expf((cv[s] - m) * TSOFT);
        float invS = 1.0f / sum;
        for (int s = 0; s < cnt; s++) {
            int j = ci[s];
            float w = expf((cv[s] - m) * TSOFT) * invS;
            int src = map ? map[j] : j;
            const float* vr = V + (size_t)src * vd;
#pragma unroll
            for (int q = 0; q < 8; q++)
                if (q < nq) acc[q] += w * vr[t + q * 256];
        }
    } else {
        float w = 1.0f / (float)N_CLS;
        for (int j = 0; j < N_CLS; j++) {
            int src = map ? map[j] : j;
            const float* vr = V + (size_t)src * vd;
#pragma unroll
            for (int q = 0; q < 8; q++)
                if (q < nq) acc[q] += w * vr[t + q * 256];
        }
    }

    float o[8];
#pragma unroll
    for (int q = 0; q < 8; q++)
        if (q < nq) {
            o[q] = round_out ? f2tf(acc[q]) : acc[q];
            out[(size_t)i * vd + t + q * 256] = o[q];
        }

    if (rn_out) {
        float ss = 0.f;
#pragma unroll
        for (int q = 0; q < 8; q++)
            if (q < nq) ss += o[q] * o[q];
        sred[t] = ss;
        __syncthreads();
        for (int w = 128; w > 0; w >>= 1) {
            if (t < w) sred[t] += sred[t + w];
            __syncthreads();
        }
        if (t == 0) rn_out[i] = rsqrtf(fmaxf(sred[0], 1e-16f));
    }
}

// ---------------- launch ----------------
extern "C" void kernel_launch(void* const* d_in, const int* in_sizes, int n_in,
                              void* d_out, int out_size) {
    const float* image      = (const float*)d_in[0];
    const float* attributes = (const float*)d_in[1];
    const int*   labels     = (const int*)d_in[2];
    const int*   tpl        = (const int*)d_in[3];
    const float* ga         = (const float*)d_in[4];
    const float* gv         = (const float*)d_in[5];
    float* out = (float*)d_out;

    float *a1p, *a2p, *b2p, *rnp, *rsqp, *prp;
    cudaGetSymbolAddress((void**)&a1p, g_a1);
    cudaGetSymbolAddress((void**)&a2p, g_a2);
    cudaGetSymbolAddress((void**)&b2p, g_b2);
    cudaGetSymbolAddress((void**)&rnp, g_rnorm);
    cudaGetSymbolAddress((void**)&rsqp, g_rowsq);
    cudaGetSymbolAddress((void**)&prp, g_protos);

    static cudaStream_t s_proto = nullptr;
    static cudaEvent_t ev_fork = nullptr, ev_proto = nullptr;
    if (!s_proto) {
        cudaStreamCreateWithFlags(&s_proto, cudaStreamNonBlocking);
        cudaEventCreateWithFlags(&ev_fork, cudaEventDisableTiming);
        cudaEventCreateWithFlags(&ev_proto, cudaEventDisableTiming);
        cudaFuncSetAttribute(gemm_nt_cand,
                             cudaFuncAttributeMaxDynamicSharedMemorySize, SMEM_NT);
        cudaFuncSetAttribute(gemm_nn_dual,
                             cudaFuncAttributeMaxDynamicSharedMemorySize, SMEM_NN);
    }

    const int NTRI = (N_CLS / 128) * (N_CLS / 128 + 1) / 2;  // 136

    // ---- fork proto chain ----
    cudaEventRecord(ev_fork, 0);
    cudaStreamWaitEvent(s_proto, ev_fork, 0);

    countscan_kernel<<<1, 1024, 0, s_proto>>>(labels);
    scatter_kernel<<<N_IMG / 256, 256, 0, s_proto>>>(labels);
    proto_kernel<<<PROTO_GRID, 256, 0, s_proto>>>(image);
    cudaEventRecord(ev_proto, s_proto);

    // ---- attention critical path (main stream): 5 nodes ----
    gemm_nn_dual<<<dim3(HC / 64, N_CLS / 128, 2), 256, SMEM_NN>>>(
        attributes, ga, gv, a1p, b2p, N_CLS, HC, ATT_D);

    gemm_nt_cand<<<NTRI, 256, SMEM_NT>>>(a1p, rsqp, 1, N_CLS, HC);

    cand_gather_kernel<<<N_CLS, 256>>>(b2p, nullptr, a2p, HC, 1, rnp, 0);

    gemm_nt_cand<<<NTRI, 256, SMEM_NT>>>(a2p, rnp, 0, N_CLS, HC);

    cudaStreamWaitEvent(0, ev_proto, 0);
    cand_gather_kernel<<<N_CLS, 256>>>(prp, tpl, out, IMG_D, 0, nullptr, 1);
}